// round 10
// baseline (speedup 1.0000x reference)
#include <cuda_runtime.h>
#include <cstdint>

// Problem constants
#define BATCH 4
#define NPTS  200000
#define NGRID 128            // NX = NY = NZ = 128
#define NVOX  (BATCH * NGRID * NGRID * NGRID)   // 8,388,608 voxels
#define NWORDS (NVOX / 32)                      // 262,144 uint32 per tensor

// Scratch: 2 tensors x 1 MB bitmask (static device array, no alloc).
// Invariant: zero at entry to kernel_launch. Zero-initialized at module load;
// expand_kernel self-clears (full-line, block-exclusive) at the end of every
// invocation, so correctness run and every graph replay see identical state.
__device__ unsigned int g_mask[2][NWORDS];

// ---------------------------------------------------------------------------
// Kernel 1: scatter points into occupancy bitmasks (atomicOr, L2-resident).
// grid.y = tensor index t; one thread per point.
//
// Numeric model (verified rel_err == 0.0 since R3): XLA arcp form
//   q = (p - 0.5*v) * (1/v),  with 1/v correctly rounded (__fdiv_rn).
// Per-thread divides are free here (R8 measured: precompute saved nothing;
// scatter is point-load bound). rintf = round-half-even = jnp.round.
// ---------------------------------------------------------------------------
__device__ __forceinline__ int voxel_coord(float p, float v, float rinv) {
    float half    = __fmul_rn(v, 0.5f);        // exact
    float shifted = __fsub_rn(p, half);        // IEEE sub
    float q       = __fmul_rn(shifted, rinv);  // multiply by CR reciprocal
    return (int)rintf(q) + 64;
}

__global__ void scatter_kernel(const float* __restrict__ pts_a,
                               const float* __restrict__ pts_b,
                               const float* __restrict__ vs) {
    unsigned idx = blockIdx.x * blockDim.x + threadIdx.x;  // over BATCH*NPTS
    if (idx >= BATCH * NPTS) return;
    const int t = blockIdx.y;
    const float* __restrict__ pts = (t == 0) ? pts_a : pts_b;

    const int b = idx / NPTS;
    const float vx = __ldg(&vs[b * 3 + 0]);
    const float vy = __ldg(&vs[b * 3 + 1]);
    const float vz = __ldg(&vs[b * 3 + 2]);

    const float rx = __fdiv_rn(1.0f, vx);      // correctly-rounded reciprocal
    const float ry = __fdiv_rn(1.0f, vy);
    const float rz = __fdiv_rn(1.0f, vz);

    const float px = pts[(size_t)idx * 3 + 0];
    const float py = pts[(size_t)idx * 3 + 1];
    const float pz = pts[(size_t)idx * 3 + 2];

    const int i = voxel_coord(px, vx, rx);
    const int j = voxel_coord(py, vy, ry);
    const int k = voxel_coord(pz, vz, rz);

    if ((unsigned)i < NGRID && (unsigned)j < NGRID && (unsigned)k < NGRID) {
        const unsigned lin = (((unsigned)b * NGRID + i) * NGRID + j) * NGRID + k;
        atomicOr(&g_mask[t][lin >> 5], 1u << (lin & 31u));
    }
}

// ---------------------------------------------------------------------------
// Kernel 2: expand bitmasks into the output tensor AND self-clear the mask.
//
// Layout: each 256-thread block owns 1024 CONSECUTIVE voxels = exactly one
// 128 B mask line per tensor (32 words, line-aligned). Within the block,
// warp k owns voxels [base+k*128, base+k*128+128) = mask words w0..w0+3;
// thread element u hits voxel base+k*128+u*32+lane, so every STG.128 is
// lane-contiguous (full 512 B per instruction — the proven-fast pattern).
//
// Self-clear (safe, unlike R4-R6): after __syncthreads(), warp 0 stores zeros
// to the block's ENTIRE private 128 B line (coalesced full-line store, no
// partial-line write into a line other blocks are reading — that partial-line
// cross-warp interference was the R4-R6 toxicity).
// ---------------------------------------------------------------------------
__global__ void expand_kernel(float4* __restrict__ out,
                              const float* __restrict__ emb) {
    const unsigned block_base = blockIdx.x * 1024u;       // first voxel of block
    const unsigned warp = threadIdx.x >> 5;
    const unsigned lane = threadIdx.x & 31u;
    const unsigned base = block_base + warp * 128u;       // first voxel of warp
    const unsigned w0   = base >> 5;                      // first of 4 words

    unsigned wa[4], wb[4];
#pragma unroll
    for (int u = 0; u < 4; u++) {
        wa[u] = g_mask[0][w0 + u];                        // warp-broadcast loads
        wb[u] = g_mask[1][w0 + u];
    }

    __syncthreads();                    // all 8 warps' reads of the line done
    if (warp == 0u) {                   // full-line, block-exclusive clear
        g_mask[0][(block_base >> 5) + lane] = 0u;
        g_mask[1][(block_base >> 5) + lane] = 0u;
    }

    const float e00 = __ldg(&emb[0]);
    const float e01 = __ldg(&emb[1]);
    const float e10 = __ldg(&emb[2]);
    const float e11 = __ldg(&emb[3]);

#pragma unroll
    for (int u = 0; u < 4; u++) {
        const bool a = (wa[u] >> lane) & 1u;
        const bool c = (wb[u] >> lane) & 1u;
        out[base + (unsigned)u * 32u + lane] =
            make_float4(a ? e00 : 0.0f, a ? e01 : 0.0f,
                        c ? e10 : 0.0f, c ? e11 : 0.0f);
    }
}

// ---------------------------------------------------------------------------
// Launch (2 graph nodes)
// Inputs (metadata order): points_a [4,200000,3] f32, points_b [4,200000,3] f32,
//                          neck_voxel_sizes [4,3] f32, embedding_weight [2,2] f32
// Output: [4,128,128,128,4] f32  (33,554,432 floats)
// ---------------------------------------------------------------------------
extern "C" void kernel_launch(void* const* d_in, const int* in_sizes, int n_in,
                              void* d_out, int out_size) {
    const float* pts_a = (const float*)d_in[0];
    const float* pts_b = (const float*)d_in[1];
    const float* vs    = (const float*)d_in[2];
    const float* emb   = (const float*)d_in[3];

    // 1) scatter both point sets into the bitmasks (mask zero on entry)
    dim3 sgrid((BATCH * NPTS + 255) / 256, 2);
    scatter_kernel<<<sgrid, 256>>>(pts_a, pts_b, vs);

    // 2) expand + self-clear: NVOX/1024 = 8192 blocks, 4 float4 stores/thread
    expand_kernel<<<NVOX / 1024, 256>>>((float4*)d_out, emb);
}

// round 11
// speedup vs baseline: 1.2259x; 1.2259x over previous
#include <cuda_runtime.h>
#include <cstdint>

// Problem constants
#define BATCH 4
#define NPTS  200000
#define NGRID 128            // NX = NY = NZ = 128
#define NVOX  (BATCH * NGRID * NGRID * NGRID)   // 8,388,608 voxels
#define NWORDS (NVOX / 32)                      // 262,144 uint32 per tensor

// Scratch: 2 tensors x 1 MB bitmask (static device array, no alloc).
// ENTRY INVARIANT: mask is all-zero when kernel_launch begins.
//   - first call: guaranteed by module-load zero-initialization
//   - later calls/replays: guaranteed by the trailing clear_kernel
// Expand NEVER writes the mask (R4/R6/R10 all proved in-expand clears are
// toxic to the streaming-store bandwidth, regardless of write granularity).
__device__ unsigned int g_mask[2][NWORDS];

// ---------------------------------------------------------------------------
// Kernel 1: scatter points into occupancy bitmasks (atomicOr, L2-resident).
// grid.y = tensor index t; one thread per point.
//
// Numeric model (verified rel_err == 0.0 since R3): XLA arcp form
//   q = (p - 0.5*v) * (1/v),  with 1/v correctly rounded (__fdiv_rn).
// rintf = round-half-even = jnp.round.
// ---------------------------------------------------------------------------
__device__ __forceinline__ int voxel_coord(float p, float v, float rinv) {
    float half    = __fmul_rn(v, 0.5f);        // exact
    float shifted = __fsub_rn(p, half);        // IEEE sub
    float q       = __fmul_rn(shifted, rinv);  // multiply by CR reciprocal
    return (int)rintf(q) + 64;
}

__global__ void scatter_kernel(const float* __restrict__ pts_a,
                               const float* __restrict__ pts_b,
                               const float* __restrict__ vs) {
    unsigned idx = blockIdx.x * blockDim.x + threadIdx.x;  // over BATCH*NPTS
    if (idx >= BATCH * NPTS) return;
    const int t = blockIdx.y;
    const float* __restrict__ pts = (t == 0) ? pts_a : pts_b;

    const int b = idx / NPTS;
    const float vx = __ldg(&vs[b * 3 + 0]);
    const float vy = __ldg(&vs[b * 3 + 1]);
    const float vz = __ldg(&vs[b * 3 + 2]);

    const float rx = __fdiv_rn(1.0f, vx);      // correctly-rounded reciprocal
    const float ry = __fdiv_rn(1.0f, vy);
    const float rz = __fdiv_rn(1.0f, vz);

    const float px = pts[(size_t)idx * 3 + 0];
    const float py = pts[(size_t)idx * 3 + 1];
    const float pz = pts[(size_t)idx * 3 + 2];

    const int i = voxel_coord(px, vx, rx);
    const int j = voxel_coord(py, vy, ry);
    const int k = voxel_coord(pz, vz, rz);

    if ((unsigned)i < NGRID && (unsigned)j < NGRID && (unsigned)k < NGRID) {
        const unsigned lin = (((unsigned)b * NGRID + i) * NGRID + j) * NGRID + k;
        atomicOr(&g_mask[t][lin >> 5], 1u << (lin & 31u));
    }
}

// ---------------------------------------------------------------------------
// Kernel 2: expand bitmasks into the output tensor (READ-ONLY on the mask).
// Exact R9 form (measured ~26 us): each warp owns 128 consecutive voxels;
// element u of each lane hits base + u*32 + lane, so every STG.128 is
// lane-contiguous (full 512 B per warp instruction), 4-deep store ILP,
// 8 broadcast mask LDGs amortized over 4 stores.
// ---------------------------------------------------------------------------
__global__ void expand_kernel(float4* __restrict__ out,
                              const float* __restrict__ emb) {
    const unsigned gwarp = (blockIdx.x * blockDim.x + threadIdx.x) >> 5;
    const unsigned lane  = threadIdx.x & 31u;
    const unsigned base  = gwarp * 128u;     // first voxel of this warp
    const unsigned w0    = base >> 5;        // first of 4 mask words

    unsigned wa[4], wb[4];
#pragma unroll
    for (int u = 0; u < 4; u++) {
        wa[u] = g_mask[0][w0 + u];           // warp-broadcast loads
        wb[u] = g_mask[1][w0 + u];
    }

    const float e00 = __ldg(&emb[0]);
    const float e01 = __ldg(&emb[1]);
    const float e10 = __ldg(&emb[2]);
    const float e11 = __ldg(&emb[3]);

#pragma unroll
    for (int u = 0; u < 4; u++) {
        const bool a = (wa[u] >> lane) & 1u;
        const bool c = (wb[u] >> lane) & 1u;
        out[base + (unsigned)u * 32u + lane] =
            make_float4(a ? e00 : 0.0f, a ? e01 : 0.0f,
                        c ? e10 : 0.0f, c ? e11 : 0.0f);
    }
}

// ---------------------------------------------------------------------------
// Kernel 3 (trailing): clear the bitmasks, restoring the entry invariant for
// the next invocation. Runs AFTER expand, so it never interferes with the
// streaming stores. 2 MB of uint4 stores (mostly L2-resident lines).
// ---------------------------------------------------------------------------
__global__ void clear_kernel() {
    const unsigned idx = blockIdx.x * blockDim.x + threadIdx.x;  // < 131072
    ((uint4*)g_mask)[idx] = make_uint4(0u, 0u, 0u, 0u);
}

// ---------------------------------------------------------------------------
// Launch (3 graph nodes: scatter -> expand -> clear)
// Inputs (metadata order): points_a [4,200000,3] f32, points_b [4,200000,3] f32,
//                          neck_voxel_sizes [4,3] f32, embedding_weight [2,2] f32
// Output: [4,128,128,128,4] f32  (33,554,432 floats)
// ---------------------------------------------------------------------------
extern "C" void kernel_launch(void* const* d_in, const int* in_sizes, int n_in,
                              void* d_out, int out_size) {
    const float* pts_a = (const float*)d_in[0];
    const float* pts_b = (const float*)d_in[1];
    const float* vs    = (const float*)d_in[2];
    const float* emb   = (const float*)d_in[3];

    // 1) scatter both point sets into the bitmasks (mask zero on entry)
    dim3 sgrid((BATCH * NPTS + 255) / 256, 2);
    scatter_kernel<<<sgrid, 256>>>(pts_a, pts_b, vs);

    // 2) expand to output: NVOX/4 threads, 4 warp-strided float4 stores each
    expand_kernel<<<(NVOX / 4) / 256, 256>>>((float4*)d_out, emb);

    // 3) trailing clear: restore mask-zero invariant for the next call
    clear_kernel<<<131072 / 256, 256>>>();
}

// round 12
// speedup vs baseline: 1.2349x; 1.0073x over previous
#include <cuda_runtime.h>
#include <cstdint>

// Problem constants
#define BATCH 4
#define NPTS  200000
#define NGRID 128            // NX = NY = NZ = 128
#define NVOX  (BATCH * NGRID * NGRID * NGRID)   // 8,388,608 voxels
#define NWORDS (NVOX / 32)                      // 262,144 uint32 per tensor

// Scratch: 2 tensors x 1 MB bitmask (static device array, no alloc).
// ENTRY INVARIANT: mask is all-zero when kernel_launch begins.
//   - first call: module-load zero-initialization
//   - later calls/replays: trailing clear_kernel
// Expand NEVER writes the mask (R4/R6/R10: in-expand clears are toxic to the
// streaming-store bandwidth at every write granularity tried).
__device__ unsigned int g_mask[2][NWORDS];

// ---------------------------------------------------------------------------
// Kernel 1: scatter points into occupancy bitmasks (atomicOr, L2-resident).
// grid = (ceil(NPTS/256), BATCH, 2): batch and tensor come from block coords,
// so there is NO per-thread integer division. The 3 correctly-rounded
// reciprocals are computed once per block (threads 0-2) and broadcast via
// shared memory — bit-identical values to the per-thread __fdiv_rn used since
// R3 (verified rel_err == 0.0), ~30 fewer instructions per thread.
//
// Numeric model: XLA arcp form  q = (p - 0.5*v) * (1/v), 1/v correctly
// rounded. rintf = round-half-even = jnp.round.
// ---------------------------------------------------------------------------
__device__ __forceinline__ int voxel_coord(float p, float v, float rinv) {
    float half    = __fmul_rn(v, 0.5f);        // exact
    float shifted = __fsub_rn(p, half);        // IEEE sub
    float q       = __fmul_rn(shifted, rinv);  // multiply by CR reciprocal
    return (int)rintf(q) + 64;
}

__global__ void scatter_kernel(const float* __restrict__ pts_a,
                               const float* __restrict__ pts_b,
                               const float* __restrict__ vs) {
    const int b = blockIdx.y;                  // batch
    const int t = blockIdx.z;                  // tensor (0=a, 1=b)

    __shared__ float s_v[3], s_r[3];
    if (threadIdx.x < 3u) {
        const float v = vs[b * 3 + threadIdx.x];
        s_v[threadIdx.x] = v;
        s_r[threadIdx.x] = __fdiv_rn(1.0f, v); // CR reciprocal, once per block
    }
    __syncthreads();

    const unsigned p = blockIdx.x * blockDim.x + threadIdx.x;
    if (p >= NPTS) return;

    const float* __restrict__ pts =
        ((t == 0) ? pts_a : pts_b) + (size_t)b * (NPTS * 3);

    const float px = pts[(size_t)p * 3 + 0];
    const float py = pts[(size_t)p * 3 + 1];
    const float pz = pts[(size_t)p * 3 + 2];

    const int i = voxel_coord(px, s_v[0], s_r[0]);
    const int j = voxel_coord(py, s_v[1], s_r[1]);
    const int k = voxel_coord(pz, s_v[2], s_r[2]);

    if ((unsigned)i < NGRID && (unsigned)j < NGRID && (unsigned)k < NGRID) {
        const unsigned lin = (((unsigned)b * NGRID + i) * NGRID + j) * NGRID + k;
        atomicOr(&g_mask[t][lin >> 5], 1u << (lin & 31u));
    }
}

// ---------------------------------------------------------------------------
// Kernel 2: expand bitmasks into the output tensor (READ-ONLY on the mask).
// R9 warp-strided form (measured ~19-20 us): each warp owns 128 consecutive
// voxels; element u of each lane hits base + u*32 + lane -> every STG.128 is
// lane-contiguous (full 512 B per warp instruction), 4-deep store ILP.
// Mask loads: the warp's 4 consecutive words per tensor are 16 B aligned ->
// ONE broadcast LDG.128 per tensor (was 8 scalar LDGs), cutting LSU issue.
// ---------------------------------------------------------------------------
__global__ void expand_kernel(float4* __restrict__ out,
                              const float* __restrict__ emb) {
    const unsigned gwarp = (blockIdx.x * blockDim.x + threadIdx.x) >> 5;
    const unsigned lane  = threadIdx.x & 31u;
    const unsigned base  = gwarp * 128u;     // first voxel of this warp
    const unsigned w0    = base >> 5;        // first of 4 mask words (16B align)

    const uint4 va = *(const uint4*)&g_mask[0][w0];  // broadcast LDG.128
    const uint4 vb = *(const uint4*)&g_mask[1][w0];
    const unsigned wa[4] = {va.x, va.y, va.z, va.w};
    const unsigned wb[4] = {vb.x, vb.y, vb.z, vb.w};

    const float e00 = __ldg(&emb[0]);
    const float e01 = __ldg(&emb[1]);
    const float e10 = __ldg(&emb[2]);
    const float e11 = __ldg(&emb[3]);

#pragma unroll
    for (int u = 0; u < 4; u++) {
        const bool a = (wa[u] >> lane) & 1u;
        const bool c = (wb[u] >> lane) & 1u;
        out[base + (unsigned)u * 32u + lane] =
            make_float4(a ? e00 : 0.0f, a ? e01 : 0.0f,
                        c ? e10 : 0.0f, c ? e11 : 0.0f);
    }
}

// ---------------------------------------------------------------------------
// Kernel 3 (trailing): clear the bitmasks, restoring the entry invariant for
// the next invocation. Runs AFTER expand — never touches the store stream.
// ---------------------------------------------------------------------------
__global__ void clear_kernel() {
    const unsigned idx = blockIdx.x * blockDim.x + threadIdx.x;  // < 131072
    ((uint4*)g_mask)[idx] = make_uint4(0u, 0u, 0u, 0u);
}

// ---------------------------------------------------------------------------
// Launch (3 graph nodes: scatter -> expand -> clear)
// Inputs (metadata order): points_a [4,200000,3] f32, points_b [4,200000,3] f32,
//                          neck_voxel_sizes [4,3] f32, embedding_weight [2,2] f32
// Output: [4,128,128,128,4] f32  (33,554,432 floats)
// ---------------------------------------------------------------------------
extern "C" void kernel_launch(void* const* d_in, const int* in_sizes, int n_in,
                              void* d_out, int out_size) {
    const float* pts_a = (const float*)d_in[0];
    const float* pts_b = (const float*)d_in[1];
    const float* vs    = (const float*)d_in[2];
    const float* emb   = (const float*)d_in[3];

    // 1) scatter: (ceil(NPTS/256), BATCH, 2) blocks
    dim3 sgrid((NPTS + 255) / 256, BATCH, 2);
    scatter_kernel<<<sgrid, 256>>>(pts_a, pts_b, vs);

    // 2) expand to output: NVOX/4 threads, 4 warp-strided float4 stores each
    expand_kernel<<<(NVOX / 4) / 256, 256>>>((float4*)d_out, emb);

    // 3) trailing clear: restore mask-zero invariant for the next call
    clear_kernel<<<131072 / 256, 256>>>();
}